// round 12
// baseline (speedup 1.0000x reference)
#include <cuda_runtime.h>
#include <cstdint>

// ---------------------------------------------------------------------------
// StoX_Conv2d: 4-bit-weight / 4-plane-binarized-activation conv + per-chunk
// BatchNorm + stochastic MTJ binarization (exact JAX threefry reproduction).
// R11: 8-chain dp4a kG with packed stores; integer-threshold binarize table.
// ---------------------------------------------------------------------------

#define BATCH 8
#define CIN   64
#define LDIM  1024          // 32*32
#define OUTC  128
#define ABITS 4
#define GCH   9             // NUM_CHUNKS
#define CKTOT 576           // CIN*9
#define NTOT  32            // ABITS*BATCH
#define PSTR  1160          // padded 34x34 plane stride (1156 -> 1160, word aligned)
#define TROW  904           // table row stride (897 entries padded)

// ---- static device scratch (allocation-free rule: __device__ globals) -----
__device__ __align__(16) signed char d_SP[NTOT * CIN * PSTR];        // padded sign planes
__device__ __align__(16) int         d_Wp[144 * OUTC];               // packed quantized weights *7
__device__ __align__(16) short       d_t7[GCH * NTOT * OUTC * LDIM]; // 7*lt exact int
__device__ int                       d_S1[GCH * OUTC];               // exact sum(m)
__device__ unsigned long long        d_S2[GCH * OUTC];               // exact sum(m^2)
__device__ __align__(16) int         d_Ti[GCH * OUTC * TROW];        // binarize thresholds

struct Keys { unsigned v[2 * GCH]; };

// ---------------- Threefry2x32 (matches jax/_src/prng.py bit-exactly) ------
__host__ __device__ __forceinline__ unsigned rotl32(unsigned x, int r) {
#if defined(__CUDA_ARCH__)
    return __funnelshift_l(x, x, r);
#else
    return (x << r) | (x >> (32 - r));
#endif
}

__host__ __device__ __forceinline__ void tf2x32(unsigned k0, unsigned k1,
                                                unsigned x0, unsigned x1,
                                                unsigned& o0, unsigned& o1) {
    unsigned k2 = k0 ^ k1 ^ 0x1BD11BDAu;
    x0 += k0; x1 += k1;
#define TF_R(r) { x0 += x1; x1 = rotl32(x1, r); x1 ^= x0; }
    TF_R(13) TF_R(15) TF_R(26) TF_R(6)
    x0 += k1; x1 += k2 + 1u;
    TF_R(17) TF_R(29) TF_R(16) TF_R(24)
    x0 += k2; x1 += k0 + 2u;
    TF_R(13) TF_R(15) TF_R(26) TF_R(6)
    x0 += k0; x1 += k1 + 3u;
    TF_R(17) TF_R(29) TF_R(16) TF_R(24)
    x0 += k1; x1 += k2 + 4u;
    TF_R(13) TF_R(15) TF_R(26) TF_R(6)
    x0 += k2; x1 += k0 + 5u;
#undef TF_R
    o0 = x0; o1 = x1;
}

// ---------------- XLA EmitTanh f32 rational (un-fused mul/add) -------------
__device__ __forceinline__ float tanh_xla(float xin) {
    float x = fminf(fmaxf(xin, -9.0f), 9.0f);
    float x2 = __fmul_rn(x, x);
    float p = -2.76076847742355e-16f;
    p = __fadd_rn(__fmul_rn(x2, p),  2.00018790482477e-13f);
    p = __fadd_rn(__fmul_rn(x2, p), -8.60467152213735e-11f);
    p = __fadd_rn(__fmul_rn(x2, p),  5.12229709037114e-08f);
    p = __fadd_rn(__fmul_rn(x2, p),  1.48572235717979e-05f);
    p = __fadd_rn(__fmul_rn(x2, p),  6.37261928875436e-04f);
    p = __fadd_rn(__fmul_rn(x2, p),  4.89352455891786e-03f);
    float num = __fmul_rn(x, p);
    float q = 1.19825839466702e-06f;
    q = __fadd_rn(__fmul_rn(x2, q), 1.18534705686654e-04f);
    q = __fadd_rn(__fmul_rn(x2, q), 2.26843463243900e-03f);
    q = __fadd_rn(__fmul_rn(x2, q), 4.89352518554385e-03f);
    float r = __fdiv_rn(num, q);
    return (fabsf(xin) < 0.0004f) ? xin : r;
}

// ---------------- kZ: zero stat accumulators -------------------------------
__global__ void kZ() {
    int i = blockIdx.x * 256 + threadIdx.x;
    if (i < GCH * OUTC) { d_S1[i] = 0; d_S2[i] = 0ull; }
}

// ---------------- kPrep: sign planes (fill + interior in one pass) ---------
__global__ void kPrep(const float* __restrict__ inp) {
    int i = blockIdx.x * 256 + threadIdx.x;         // over 512*1156
    if (i >= BATCH * CIN * 1156) return;
    int bc = i / 1156, p = i - bc * 1156;
    int y = p / 34, x = p - y * 34;
    const int AS = 512 * PSTR;                      // a-plane stride
    int base = bc * PSTR + p;
    if (y == 0 || y == 33 || x == 0 || x == 33) {
        d_SP[base] = 1;
        d_SP[AS + base] = -1;
        d_SP[2 * AS + base] = -1;
        d_SP[3 * AS + base] = -1;
    } else {
        float v = inp[(bc << 10) + (y - 1) * 32 + (x - 1)];
        float r = fminf(fmaxf(v, -1.0f), 1.0f);
        float half = 0.5f;
#pragma unroll
        for (int a = 0; a < ABITS; ++a) {
            bool pos = (r >= 0.0f);
            d_SP[a * AS + base] = pos ? 1 : -1;
            r = __fsub_rn(r, pos ? half : -half);
            half = __fmul_rn(half, 0.5f);
        }
    }
}

// ---------------- kW: weight standardize + 4-bit quantize ------------------
__global__ void kW(const float* __restrict__ wgt) {
    int o = blockIdx.x;                 // 128
    int t = threadIdx.x;                // 64
    __shared__ double red[64], red2[64];
    __shared__ float s_mean, s_std;
    const float* wr = wgt + o * CKTOT;

    double s = 0.0;
    for (int i = t; i < CKTOT; i += 64) s += (double)wr[i];
    red[t] = s; __syncthreads();
    for (int st = 32; st; st >>= 1) { if (t < st) red[t] += red[t + st]; __syncthreads(); }
    if (!t) s_mean = (float)(red[0] / 576.0);
    __syncthreads();
    float mf = s_mean;

    double s1 = 0.0, s2 = 0.0;
    for (int i = t; i < CKTOT; i += 64) {
        float bw = __fsub_rn(wr[i], mf);
        s1 += (double)bw; s2 += (double)bw * (double)bw;
    }
    red[t] = s1; red2[t] = s2; __syncthreads();
    for (int st = 32; st; st >>= 1) {
        if (t < st) { red[t] += red[t + st]; red2[t] += red2[t + st]; }
        __syncthreads();
    }
    if (!t) {
        double mu = red[0] / 576.0;
        double var = (red2[0] - 576.0 * mu * mu) / 575.0;  // ddof=1
        s_std = (float)sqrt(var);
    }
    __syncthreads();
    float stdf = s_std;

    for (int i = t; i < CKTOT; i += 64) {
        float bw = __fsub_rn(wr[i], mf);
        float c = fminf(fmaxf(__fdiv_rn(bw, stdf), -1.0f), 1.0f);
        int m = (int)rintf(__fmul_rn(c, 7.0f));   // round-half-even, like jnp.round
        ((signed char*)d_Wp)[(((unsigned)i >> 2) * OUTC + o) * 4 + (i & 3)] = (signed char)m;
    }
}

// ---------------- kG: fused unfold + exact int8 GEMM (7*lt) ----------------
// grid (2 l-halves, 32 n, 9 g), 256 threads; each thread: adjacent l-pair,
// 2 outputs/iter, k split in halves -> 8 independent dp4a chains of depth 8.
__global__ void __launch_bounds__(256) kG() {
    __shared__ __align__(16) int ws[OUTC][16];
    __shared__ __align__(16) signed char sgn[9 * PSTR];   // <= 9 channels
    int g = blockIdx.z, n = blockIdx.y, lh = blockIdx.x;
    int tid = threadIdx.x;

    for (int i = tid; i < OUTC * 16; i += 256) {
        int o = i >> 4, q = i & 15;
        ws[o][q] = d_Wp[(16 * g + q) * OUTC + o];
    }
    int c_lo = (64 * g) / 9;
    int cn = min(9, CIN - c_lo);
    {
        const int* src = (const int*)(d_SP + (n * CIN + c_lo) * PSTR);
        int* dst = (int*)sgn;
        int words = cn * (PSTR / 4);
        for (int i = tid; i < words; i += 256) dst[i] = src[i];
    }
    __syncthreads();

    int l0 = lh * 512 + 2 * tid;
    int l1 = l0 + 1;
    int px0 = (l0 >> 5) * 34 + (l0 & 31);
    int px1 = (l1 >> 5) * 34 + (l1 & 31);

    int A0[16], A1[16];
#pragma unroll
    for (int q = 0; q < 16; ++q) { A0[q] = 0; A1[q] = 0; }
#pragma unroll
    for (int q = 0; q < 16; ++q) {
#pragma unroll
        for (int s = 0; s < 4; ++s) {
            int ck = 64 * g + q * 4 + s;
            int cq = ck / 9;
            int kp = ck - cq * 9;
            int dy = kp / 3, dx = kp - dy * 3;
            int boff = (cq - c_lo) * PSTR + dy * 34 + dx;   // block-uniform
            unsigned b0 = (unsigned char)sgn[boff + px0];
            unsigned b1 = (unsigned char)sgn[boff + px1];
            A0[q] |= b0 << (8 * s);
            A1[q] |= b1 << (8 * s);
        }
    }

    short* tb = d_t7 + ((g * NTOT + n) << 17) + l0;
#pragma unroll 2
    for (int o = 0; o < OUTC; o += 2) {
        int4 wa0 = *(const int4*)&ws[o][0];
        int4 wa1 = *(const int4*)&ws[o][4];
        int4 wa2 = *(const int4*)&ws[o][8];
        int4 wa3 = *(const int4*)&ws[o][12];
        int4 wb0 = *(const int4*)&ws[o + 1][0];
        int4 wb1 = *(const int4*)&ws[o + 1][4];
        int4 wb2 = *(const int4*)&ws[o + 1][8];
        int4 wb3 = *(const int4*)&ws[o + 1][12];
        // 8 independent chains (2 l x 2 o x 2 k-halves), 8 dp4a each
        int cA0 = 0, cA1 = 0, cB0 = 0, cB1 = 0;
        int dA0 = 0, dA1 = 0, dB0 = 0, dB1 = 0;
        cA0 = __dp4a(A0[0], wa0.x, cA0);  cA1 = __dp4a(A1[0], wa0.x, cA1);
        cB0 = __dp4a(A0[0], wb0.x, cB0);  cB1 = __dp4a(A1[0], wb0.x, cB1);
        dA0 = __dp4a(A0[8], wa2.x, dA0);  dA1 = __dp4a(A1[8], wa2.x, dA1);
        dB0 = __dp4a(A0[8], wb2.x, dB0);  dB1 = __dp4a(A1[8], wb2.x, dB1);
        cA0 = __dp4a(A0[1], wa0.y, cA0);  cA1 = __dp4a(A1[1], wa0.y, cA1);
        cB0 = __dp4a(A0[1], wb0.y, cB0);  cB1 = __dp4a(A1[1], wb0.y, cB1);
        dA0 = __dp4a(A0[9], wa2.y, dA0);  dA1 = __dp4a(A1[9], wa2.y, dA1);
        dB0 = __dp4a(A0[9], wb2.y, dB0);  dB1 = __dp4a(A1[9], wb2.y, dB1);
        cA0 = __dp4a(A0[2], wa0.z, cA0);  cA1 = __dp4a(A1[2], wa0.z, cA1);
        cB0 = __dp4a(A0[2], wb0.z, cB0);  cB1 = __dp4a(A1[2], wb0.z, cB1);
        dA0 = __dp4a(A0[10], wa2.z, dA0); dA1 = __dp4a(A1[10], wa2.z, dA1);
        dB0 = __dp4a(A0[10], wb2.z, dB0); dB1 = __dp4a(A1[10], wb2.z, dB1);
        cA0 = __dp4a(A0[3], wa0.w, cA0);  cA1 = __dp4a(A1[3], wa0.w, cA1);
        cB0 = __dp4a(A0[3], wb0.w, cB0);  cB1 = __dp4a(A1[3], wb0.w, cB1);
        dA0 = __dp4a(A0[11], wa2.w, dA0); dA1 = __dp4a(A1[11], wa2.w, dA1);
        dB0 = __dp4a(A0[11], wb2.w, dB0); dB1 = __dp4a(A1[11], wb2.w, dB1);
        cA0 = __dp4a(A0[4], wa1.x, cA0);  cA1 = __dp4a(A1[4], wa1.x, cA1);
        cB0 = __dp4a(A0[4], wb1.x, cB0);  cB1 = __dp4a(A1[4], wb1.x, cB1);
        dA0 = __dp4a(A0[12], wa3.x, dA0); dA1 = __dp4a(A1[12], wa3.x, dA1);
        dB0 = __dp4a(A0[12], wb3.x, dB0); dB1 = __dp4a(A1[12], wb3.x, dB1);
        cA0 = __dp4a(A0[5], wa1.y, cA0);  cA1 = __dp4a(A1[5], wa1.y, cA1);
        cB0 = __dp4a(A0[5], wb1.y, cB0);  cB1 = __dp4a(A1[5], wb1.y, cB1);
        dA0 = __dp4a(A0[13], wa3.y, dA0); dA1 = __dp4a(A1[13], wa3.y, dA1);
        dB0 = __dp4a(A0[13], wb3.y, dB0); dB1 = __dp4a(A1[13], wb3.y, dB1);
        cA0 = __dp4a(A0[6], wa1.z, cA0);  cA1 = __dp4a(A1[6], wa1.z, cA1);
        cB0 = __dp4a(A0[6], wb1.z, cB0);  cB1 = __dp4a(A1[6], wb1.z, cB1);
        dA0 = __dp4a(A0[14], wa3.z, dA0); dA1 = __dp4a(A1[14], wa3.z, dA1);
        dB0 = __dp4a(A0[14], wb3.z, dB0); dB1 = __dp4a(A1[14], wb3.z, dB1);
        cA0 = __dp4a(A0[7], wa1.w, cA0);  cA1 = __dp4a(A1[7], wa1.w, cA1);
        cB0 = __dp4a(A0[7], wb1.w, cB0);  cB1 = __dp4a(A1[7], wb1.w, cB1);
        dA0 = __dp4a(A0[15], wa3.w, dA0); dA1 = __dp4a(A1[15], wa3.w, dA1);
        dB0 = __dp4a(A0[15], wb3.w, dB0); dB1 = __dp4a(A1[15], wb3.w, dB1);

        short2 ra, rb;
        ra.x = (short)(cA0 + dA0); ra.y = (short)(cA1 + dA1);
        rb.x = (short)(cB0 + dB0); rb.y = (short)(cB1 + dB1);
        *(short2*)(tb + (o << 10)) = ra;
        *(short2*)(tb + ((o + 1) << 10)) = rb;
    }
}

// ---------------- kStats: exact BN sums per (g,o), high-MLP + atomics ------
__global__ void __launch_bounds__(128) kStats() {
    int go = blockIdx.x;            // 0..1151
    int g = go >> 7, o = go & 127;
    int ng = blockIdx.y;            // 0..7 -> n = ng*4 + i
    int t = threadIdx.x;            // 128 (one int4 per n-slab)
    const short* base = d_t7 + ((g * NTOT + ng * 4) << 17) + (o << 10);

    int4 v0 = ((const int4*)(base          ))[t];
    int4 v1 = ((const int4*)(base + (1<<17)))[t];
    int4 v2 = ((const int4*)(base + (2<<17)))[t];
    int4 v3 = ((const int4*)(base + (3<<17)))[t];

    int s1 = 0, s2 = 0;   // per-thread: 32 values, |m|<=448 -> s2 <= 6.4e6
#define ACC(w) { int mA = (short)((w) & 0xFFFF); int mB = ((w) >> 16); \
                 s1 += mA + mB; s2 += mA * mA + mB * mB; }
    ACC(v0.x) ACC(v0.y) ACC(v0.z) ACC(v0.w)
    ACC(v1.x) ACC(v1.y) ACC(v1.z) ACC(v1.w)
    ACC(v2.x) ACC(v2.y) ACC(v2.z) ACC(v2.w)
    ACC(v3.x) ACC(v3.y) ACC(v3.z) ACC(v3.w)
#undef ACC

#pragma unroll
    for (int d = 16; d; d >>= 1) {
        s1 += __shfl_xor_sync(0xFFFFFFFFu, s1, d);
        s2 += __shfl_xor_sync(0xFFFFFFFFu, s2, d);
    }
    __shared__ int r1[4], r2[4];
    int w = t >> 5;
    if ((t & 31) == 0) { r1[w] = s1; r2[w] = s2; }
    __syncthreads();
    if (t == 0) {
        int t1 = r1[0] + r1[1] + r1[2] + r1[3];
        int t2 = r2[0] + r2[1] + r2[2] + r2[3];
        atomicAdd(&d_S1[go], t1);
        atomicAdd(&d_S2[go], (unsigned long long)(long long)t2);
    }
}

// ---------------- kT: finalize BN stats + integer binarize thresholds ------
// t computed with the bit-identical op sequence; decision "t > rnd(v)" with
// rnd(v) = v*2^-22 - 1 (exact in f32) is equivalent to v < ceil((t+1)*2^22)
// computed exactly in double. t==0 (normed==0) encoded as negative sentinel.
__global__ void kT(const float* __restrict__ gamma, const float* __restrict__ beta) {
    int go = blockIdx.x;               // 0..1151
    int o = go & 127;
    __shared__ float s_mn, s_sf;
    if (threadIdx.x == 0) {
        double mu  = (double)d_S1[go] / (7.0 * 32768.0);
        double ex2 = (double)(long long)d_S2[go] / (49.0 * 32768.0);
        double var = ex2 - mu * mu;          // biased (BN train)
        s_mn = (float)mu;
        s_sf = __fsqrt_rn(__fadd_rn((float)var, 1e-5f));
    }
    __syncthreads();
    float mn = s_mn, sd = s_sf;
    float gam = gamma[o], bet = beta[o];
    for (int idx = threadIdx.x; idx < 897; idx += 256) {
        float lt = __fdiv_rn(__int2float_rn(idx - 448), 7.0f);
        float normed = __fadd_rn(__fmul_rn(__fdiv_rn(__fsub_rn(lt, mn), sd), gam), bet);
        float t = tanh_xla(__fmul_rn(normed, 4.0f));
        int Vt;
        if (t == 0.0f) {
            Vt = -1;                                   // sentinel -> s = 0
        } else {
            double thr = ((double)t + 1.0) * 4194304.0; // exact
            Vt = (int)ceil(thr);                        // v < Vt  <=>  t > rnd(v)
        }
        d_Ti[go * TROW + idx] = Vt;
    }
}

// ---------------- kE: threefry + threshold compare + recombine -------------
// one block per (o, b): 1024 threads = all l; threshold table staged per block.
__global__ void __launch_bounds__(1024) kE(float* __restrict__ out, Keys keys) {
    __shared__ int tt[GCH][TROW];
    int l = threadIdx.x;                       // 0..1023
    int o = blockIdx.x;                        // 0..127
    int b = blockIdx.y;                        // 0..7
#pragma unroll
    for (int g = 0; g < GCH; ++g)
        if (l < 897) tt[g][l] = d_Ti[(g * OUTC + o) * TROW + l];
    __syncthreads();

    int S[ABITS] = {0, 0, 0, 0};
#pragma unroll 1
    for (int g = 0; g < GCH; ++g) {
        unsigned k0 = keys.v[2 * g], k1 = keys.v[2 * g + 1];
#pragma unroll
        for (int a = 0; a < ABITS; ++a) {
            int n = a * 8 + b;
            int m7 = d_t7[((g * NTOT + n) << 17) + (o << 10) + l];
            int Vt = tt[g][m7 + 448];
            unsigned j = ((unsigned)(n * OUTC + o) << 10) + (unsigned)l;
            unsigned r0, r1; tf2x32(k0, k1, 0u, j, r0, r1);
            int v = (int)((r0 ^ r1) >> 9);
            int s = (v < Vt) ? 1 : -1;
            s = (Vt < 0) ? 0 : s;      // normed==0 -> 0
            S[a] += s;
        }
    }
    const float wts[ABITS] = {0.5f, 0.25f, 0.125f, 0.0625f};
    float acc = 0.0f;
#pragma unroll
    for (int a = 0; a < ABITS; ++a)
        acc = __fadd_rn(acc, __fmul_rn(__fdiv_rn((float)S[a], 9.0f), wts[a]));
    out[((b * OUTC + o) << 10) + l] = acc;
}

// ---------------------------------------------------------------------------
extern "C" void kernel_launch(void* const* d_in, const int* in_sizes, int n_in,
                              void* d_out, int out_size) {
    const float* inp   = (const float*)d_in[0];   // [8,64,32,32]
    const float* wgt   = (const float*)d_in[1];   // [128,64,3,3]
    const float* gamma = (const float*)d_in[2];   // [128]
    const float* beta  = (const float*)d_in[3];   // [128]
    float* out = (float*)d_out;                   // [8,128,32,32]

    // host-side key derivation: keys = split(key(42), 9) in partitionable mode
    Keys ks;
    for (int g = 0; g < GCH; ++g) {
        unsigned o0, o1;
        tf2x32(0u, 42u, 0u, (unsigned)g, o0, o1);
        ks.v[2 * g] = o0; ks.v[2 * g + 1] = o1;
    }

    kZ<<<(GCH * OUTC + 255) / 256, 256>>>();
    kPrep<<<(BATCH * CIN * 1156 + 255) / 256, 256>>>(inp);
    kW<<<OUTC, 64>>>(wgt);
    kG<<<dim3(2, NTOT, GCH), 256>>>();
    kStats<<<dim3(GCH * OUTC, 8), 128>>>();
    kT<<<GCH * OUTC, 256>>>(gamma, beta);
    kE<<<dim3(OUTC, BATCH), 1024>>>(out, ks);
}